// round 9
// baseline (speedup 1.0000x reference)
#include <cuda_runtime.h>
#include <cstdint>

// Problem constants
#define B_ROWS   65536
#define K1       1024
#define K2       512
#define K3       768
#define NPAIRS   1152                  // (K1+K2+K3)/2
#define RANK     10
#define OUTDIM   512

// ---- kernel 1 (rank projection) ----
#define T1       192
#define GRID1    304                   // 2 CTAs/SM
#define NWARPS   (GRID1 * (T1 / 32))   // 1824
#define NGROUPS  (B_ROWS / 4)          // 16384 groups of 4 rows

#define FS_ELEMS (RANK * NPAIRS)       // 11520 float2
#define SMEM1    (FS_ELEMS * 8)        // 92160 B

// ---- kernel 2 (out = y @ fout^T) ----
#define T2       256
#define RTILE    64
#define GRID2    (B_ROWS / RTILE)      // 1024

typedef unsigned long long u64;

// scratch for the intermediate y[B, RANK]
__device__ float y_buf[(size_t)B_ROWS * RANK];

// ---------- f32x2 packed helpers ----------
__device__ __forceinline__ u64 pk2(float lo, float hi) {
    u64 r; asm("mov.b64 %0, {%1, %2};" : "=l"(r) : "f"(lo), "f"(hi)); return r;
}
__device__ __forceinline__ void upk2(u64 v, float& lo, float& hi) {
    asm("mov.b64 {%0, %1}, %2;" : "=f"(lo), "=f"(hi) : "l"(v));
}
__device__ __forceinline__ u64 fma2(u64 a, u64 b, u64 c) {
    u64 d; asm("fma.rn.f32x2 %0, %1, %2, %3;" : "=l"(d) : "l"(a), "l"(b), "l"(c));
    return d;
}
__device__ __forceinline__ float hadd2(u64 v) {
    float lo, hi; upk2(v, lo, hi); return lo + hi;
}

// One segment, 4 rows per warp, depth-4 software-pipelined x prefetch.
// Half-warp h (lane>>4) owns ranks h*5..h*5+4; the 16 lanes of each half
// cover the k dimension (lane kL handles floats c*64 + kL*4 .. +3 per chunk).
// x loaded directly as ulonglong2 (two packed f32x2 operands).
template<int KSEG, int PAIR_OFF>
__device__ __forceinline__ void segment4(
    const float* __restrict__ x, int row0, int kL, int h,
    const ulonglong2* __restrict__ f2, float z[4][5])
{
    constexpr int NC = KSEG / 64;     // 64-float chunks
    static_assert(NC >= 8 && NC % 4 == 0, "chunk count");

    u64 acc[4][5];
#pragma unroll
    for (int i = 0; i < 4; i++)
#pragma unroll
        for (int j = 0; j < 5; j++) acc[i][j] = 0ull;

    const ulonglong2* q0 = reinterpret_cast<const ulonglong2*>(x + (size_t)(row0    ) * KSEG) + kL;
    const ulonglong2* q1 = reinterpret_cast<const ulonglong2*>(x + (size_t)(row0 + 1) * KSEG) + kL;
    const ulonglong2* q2 = reinterpret_cast<const ulonglong2*>(x + (size_t)(row0 + 2) * KSEG) + kL;
    const ulonglong2* q3 = reinterpret_cast<const ulonglong2*>(x + (size_t)(row0 + 3) * KSEG) + kL;

    // rotating 4-stage prefetch buffers (16 LDG.128 in flight at peak)
    ulonglong2 buf[4][4];
#pragma unroll
    for (int s = 0; s < 4; s++) {
        buf[s][0] = q0[s * 16];
        buf[s][1] = q1[s * 16];
        buf[s][2] = q2[s * 16];
        buf[s][3] = q3[s * 16];
    }

    // factor base index in ulonglong2 units for rank h*5, this segment, this lane
    const int fb = (h * 5 * NPAIRS + PAIR_OFF) / 2 + kL;

#pragma unroll 4
    for (int c = 0; c < NC - 4; c++) {
        const int s = c & 3;
        ulonglong2 v0 = buf[s][0];
        ulonglong2 v1 = buf[s][1];
        ulonglong2 v2 = buf[s][2];
        ulonglong2 v3 = buf[s][3];
        buf[s][0] = q0[(c + 4) * 16];            // refill 4 ahead
        buf[s][1] = q1[(c + 4) * 16];
        buf[s][2] = q2[(c + 4) * 16];
        buf[s][3] = q3[(c + 4) * 16];

        const ulonglong2* fp = f2 + fb + c * 16;
#pragma unroll
        for (int j = 0; j < 5; j++) {
            ulonglong2 fv = fp[j * (NPAIRS / 2)];   // LDS.128, per-half contiguous
            acc[0][j] = fma2(v0.x, fv.x, acc[0][j]);
            acc[0][j] = fma2(v0.y, fv.y, acc[0][j]);
            acc[1][j] = fma2(v1.x, fv.x, acc[1][j]);
            acc[1][j] = fma2(v1.y, fv.y, acc[1][j]);
            acc[2][j] = fma2(v2.x, fv.x, acc[2][j]);
            acc[2][j] = fma2(v2.y, fv.y, acc[2][j]);
            acc[3][j] = fma2(v3.x, fv.x, acc[3][j]);
            acc[3][j] = fma2(v3.y, fv.y, acc[3][j]);
        }
    }

    // drain the last 4 stages (NC % 4 == 0 so stages align)
#pragma unroll
    for (int c = NC - 4; c < NC; c++) {
        const int s = c & 3;
        ulonglong2 v0 = buf[s][0];
        ulonglong2 v1 = buf[s][1];
        ulonglong2 v2 = buf[s][2];
        ulonglong2 v3 = buf[s][3];
        const ulonglong2* fp = f2 + fb + c * 16;
#pragma unroll
        for (int j = 0; j < 5; j++) {
            ulonglong2 fv = fp[j * (NPAIRS / 2)];
            acc[0][j] = fma2(v0.x, fv.x, acc[0][j]);
            acc[0][j] = fma2(v0.y, fv.y, acc[0][j]);
            acc[1][j] = fma2(v1.x, fv.x, acc[1][j]);
            acc[1][j] = fma2(v1.y, fv.y, acc[1][j]);
            acc[2][j] = fma2(v2.x, fv.x, acc[2][j]);
            acc[2][j] = fma2(v2.y, fv.y, acc[2][j]);
            acc[3][j] = fma2(v3.x, fv.x, acc[3][j]);
            acc[3][j] = fma2(v3.y, fv.y, acc[3][j]);
        }
    }

    // fold even/odd halves, then butterfly over the 16-lane k-group
#pragma unroll
    for (int i = 0; i < 4; i++)
#pragma unroll
        for (int j = 0; j < 5; j++) z[i][j] = hadd2(acc[i][j]);

#pragma unroll
    for (int m = 8; m > 0; m >>= 1) {
#pragma unroll
        for (int i = 0; i < 4; i++)
#pragma unroll
            for (int j = 0; j < 5; j++)
                z[i][j] += __shfl_xor_sync(0xffffffffu, z[i][j], m);
    }
}

extern "C" __global__ void __launch_bounds__(T1, 2)
arf_k1(const float* __restrict__ x1, const float* __restrict__ x2,
       const float* __restrict__ x3,
       const float* __restrict__ f1, const float* __restrict__ f2g,
       const float* __restrict__ f3)
{
    extern __shared__ float2 f_s[];    // [RANK][NPAIRS], k-pair packed

    const int tid = threadIdx.x;

    // factor repack: f_s[r*NPAIRS + kp] = (f_seg[2k][r], f_seg[2k+1][r])
    for (int idx = tid; idx < FS_ELEMS; idx += T1) {
        int r  = idx / NPAIRS;
        int kp = idx % NPAIRS;
        const float* f; int kloc;
        if (kp < K1 / 2)              { f = f1;  kloc = 2 * kp; }
        else if (kp < (K1 + K2) / 2)  { f = f2g; kloc = 2 * (kp - K1 / 2); }
        else                          { f = f3;  kloc = 2 * (kp - (K1 + K2) / 2); }
        f_s[idx] = make_float2(f[kloc * RANK + r], f[(kloc + 1) * RANK + r]);
    }
    __syncthreads();

    const ulonglong2* fsp = reinterpret_cast<const ulonglong2*>(f_s);

    const int lane = tid & 31;
    const int kL   = lane & 15;
    const int h    = lane >> 4;
    const int gw   = (blockIdx.x * T1 + tid) >> 5;

    for (int g = gw; g < NGROUPS; g += NWARPS) {
        const int row0 = g * 4;

        float z1[4][5], zt[4][5];

        segment4<K1, 0>            (x1, row0, kL, h, fsp, z1);
        segment4<K2, K1 / 2>       (x2, row0, kL, h, fsp, zt);
#pragma unroll
        for (int i = 0; i < 4; i++)
#pragma unroll
            for (int j = 0; j < 5; j++) z1[i][j] *= zt[i][j];
        segment4<K3, (K1 + K2) / 2>(x3, row0, kL, h, fsp, zt);
#pragma unroll
        for (int i = 0; i < 4; i++)
#pragma unroll
            for (int j = 0; j < 5; j++) z1[i][j] *= zt[i][j];

        // lane (h*16 + i) writes row row0+i, ranks h*5..h*5+4
#pragma unroll
        for (int i = 0; i < 4; i++) {
            if (kL == i) {
#pragma unroll
                for (int j = 0; j < 5; j++)
                    y_buf[(size_t)(row0 + i) * RANK + h * 5 + j] = z1[i][j];
            }
        }
    }
}

// out[b, c] = sum_j y[b, j] * fout[c, j]
// 256 threads; thread t owns adjacent cols (2t, 2t+1) -> one STG.64 per row;
// 64-row tile; y transposed in smem so a row-pair is one LDS.64 broadcast;
// fout lives in registers (packed duplicate per column).
extern "C" __global__ void __launch_bounds__(T2)
arf_k2(const float* __restrict__ fout, float* __restrict__ out)
{
    __shared__ __align__(16) float yt[RANK][RTILE];   // transposed y tile

    const int t    = threadIdx.x;
    const int c0   = 2 * t;
    const int base = blockIdx.x * RTILE;

    u64 foA[RANK], foB[RANK];
#pragma unroll
    for (int j = 0; j < RANK; j++) {
        float a = fout[(size_t)c0 * RANK + j];
        float b = fout[(size_t)(c0 + 1) * RANK + j];
        foA[j] = pk2(a, a);
        foB[j] = pk2(b, b);
    }

    for (int idx = t; idx < RTILE * RANK; idx += T2) {
        int r = idx / RANK, j = idx % RANK;       // coalesced y_buf read
        yt[j][r] = y_buf[(size_t)base * RANK + idx];
    }
    __syncthreads();

#pragma unroll 4
    for (int rp = 0; rp < RTILE / 2; rp++) {
        u64 yv[RANK];
#pragma unroll
        for (int j = 0; j < RANK; j++)
            yv[j] = *reinterpret_cast<const u64*>(&yt[j][2 * rp]);  // broadcast

        u64 a = 0ull, b = 0ull;
#pragma unroll
        for (int j = 0; j < RANK; j++) {
            a = fma2(yv[j], foA[j], a);
            b = fma2(yv[j], foB[j], b);
        }
        float la, ha, lb, hb;
        upk2(a, la, ha);
        upk2(b, lb, hb);
        float2* o0 = reinterpret_cast<float2*>(out + (size_t)(base + 2 * rp) * OUTDIM);
        float2* o1 = reinterpret_cast<float2*>(out + (size_t)(base + 2 * rp + 1) * OUTDIM);
        o0[t] = make_float2(la, lb);   // STG.64, coalesced
        o1[t] = make_float2(ha, hb);
    }
}

extern "C" void kernel_launch(void* const* d_in, const int* in_sizes, int n_in,
                              void* d_out, int out_size)
{
    const float* x1   = (const float*)d_in[0];
    const float* x2   = (const float*)d_in[1];
    const float* x3   = (const float*)d_in[2];
    const float* f1   = (const float*)d_in[3];
    const float* f2   = (const float*)d_in[4];
    const float* f3   = (const float*)d_in[5];
    const float* fout = (const float*)d_in[6];
    float* out = (float*)d_out;

    cudaFuncSetAttribute(arf_k1,
                         cudaFuncAttributeMaxDynamicSharedMemorySize, SMEM1);

    arf_k1<<<GRID1, T1, SMEM1>>>(x1, x2, x3, f1, f2, f3);
    arf_k2<<<GRID2, T2>>>(fout, out);
}

// round 12
// speedup vs baseline: 1.2520x; 1.2520x over previous
#include <cuda_runtime.h>
#include <cstdint>

// Problem constants
#define B_ROWS   65536
#define K1       1024
#define K2       512
#define K3       768
#define NPAIRS   1152                  // (K1+K2+K3)/2
#define RANK     10
#define OUTDIM   512

// ---- kernel 1 (rank projection) ----
#define T1       512
#define GRID1    152                   // 1 CTA/SM
#define NWARPS   (GRID1 * (T1 / 32))   // 2432
#define NGROUPS  (B_ROWS / 4)          // 16384 groups of 4 rows

#define FS_ELEMS (RANK * NPAIRS)       // 11520 float2
#define FS_BYTES (FS_ELEMS * 8)        // 92160
#define RING_BYTES 4096                // 4 slots x 1KB per warp
#define SMEM1    (FS_BYTES + (T1 / 32) * RING_BYTES)  // 157696

// chunk counts (64-float / 256-byte chunks per row)
#define NC1      (K1 / 64)             // 16
#define NC2      (K2 / 64)             // 8
#define NC3      (K3 / 64)             // 12

// ---- kernel 2 (out = y @ fout^T) ----
#define T2       256
#define RTILE    64
#define GRID2    (B_ROWS / RTILE)      // 1024

typedef unsigned long long u64;

// scratch for the intermediate y[B, RANK]
__device__ float y_buf[(size_t)B_ROWS * RANK];

// ---------- f32x2 packed helpers ----------
__device__ __forceinline__ u64 pk2(float lo, float hi) {
    u64 r; asm("mov.b64 %0, {%1, %2};" : "=l"(r) : "f"(lo), "f"(hi)); return r;
}
__device__ __forceinline__ void upk2(u64 v, float& lo, float& hi) {
    asm("mov.b64 {%0, %1}, %2;" : "=f"(lo), "=f"(hi) : "l"(v));
}
__device__ __forceinline__ u64 fma2(u64 a, u64 b, u64 c) {
    u64 d; asm("fma.rn.f32x2 %0, %1, %2, %3;" : "=l"(d) : "l"(a), "l"(b), "l"(c));
    return d;
}
__device__ __forceinline__ float hadd2(u64 v) {
    float lo, hi; upk2(v, lo, hi); return lo + hi;
}
__device__ __forceinline__ ulonglong2 lds128(uint32_t a) {
    ulonglong2 v;
    asm volatile("ld.shared.v2.u64 {%0, %1}, [%2];"
                 : "=l"(v.x), "=l"(v.y) : "r"(a));
    return v;
}

#define CP16(DST, SRC) \
    asm volatile("cp.async.cg.shared.global [%0], [%1], 16;" \
                 :: "r"(DST), "l"(SRC) : "memory")

// issue one 1KB chunk (4 rows x 256B): this lane copies 16B of each of its
// 2 rows (rows 2h, 2h+1) into ring slot SLOT, then commits a group.
#define ISSUE(LO, HI, C, SLOT) do {                                       \
    uint32_t _d = stage_base + (uint32_t)(SLOT) * 1024u + dstoff;         \
    CP16(_d,        (LO) + (size_t)(C) * 256);                            \
    CP16(_d + 256u, (HI) + (size_t)(C) * 256);                            \
    asm volatile("cp.async.commit_group;" ::: "memory");                  \
} while (0)

#define WAITG2() asm volatile("cp.async.wait_group 2;" ::: "memory")

// consume ring slot SLOT against factor pointer FP (10 bcast LDS.128 + 40 fma2)
#define CONSUME(SLOT, FP) do {                                            \
    uint32_t _s = stage_base + (uint32_t)(SLOT) * 1024u + dstoff;         \
    ulonglong2 vA = lds128(_s);                                           \
    ulonglong2 vB = lds128(_s + 256u);                                    \
    const ulonglong2* _fp = (FP);                                         \
    _Pragma("unroll")                                                     \
    for (int j = 0; j < RANK; j++) {                                      \
        ulonglong2 fv = _fp[j * (NPAIRS / 2)];                            \
        acc[0][j] = fma2(vA.x, fv.x, acc[0][j]);                          \
        acc[0][j] = fma2(vA.y, fv.y, acc[0][j]);                          \
        acc[1][j] = fma2(vB.x, fv.x, acc[1][j]);                          \
        acc[1][j] = fma2(vB.y, fv.y, acc[1][j]);                          \
    }                                                                     \
} while (0)

// fold even/odd halves of acc into zt, zero acc
#define FOLD() do {                                                       \
    _Pragma("unroll") for (int i = 0; i < 2; i++)                         \
    _Pragma("unroll") for (int j = 0; j < RANK; j++) {                    \
        zt[i][j] = hadd2(acc[i][j]); acc[i][j] = 0ull; }                  \
} while (0)

// butterfly-reduce zt over the 16-lane k-group (stays within each half)
#define REDUCE() do {                                                     \
    _Pragma("unroll") for (int m = 8; m > 0; m >>= 1)                     \
    _Pragma("unroll") for (int i = 0; i < 2; i++)                         \
    _Pragma("unroll") for (int j = 0; j < RANK; j++)                      \
        zt[i][j] += __shfl_xor_sync(0xffffffffu, zt[i][j], m);            \
} while (0)

extern "C" __global__ void __launch_bounds__(T1, 1)
arf_k1(const float* __restrict__ x1, const float* __restrict__ x2,
       const float* __restrict__ x3,
       const float* __restrict__ f1, const float* __restrict__ f2g,
       const float* __restrict__ f3)
{
    extern __shared__ __align__(16) float2 f_s[];   // [RANK][NPAIRS] + rings

    const int tid = threadIdx.x;

    // factor repack: f_s[r*NPAIRS + kp] = (f_seg[2k][r], f_seg[2k+1][r])
    for (int idx = tid; idx < FS_ELEMS; idx += T1) {
        int r  = idx / NPAIRS;
        int kp = idx % NPAIRS;
        const float* f; int kloc;
        if (kp < K1 / 2)              { f = f1;  kloc = 2 * kp; }
        else if (kp < (K1 + K2) / 2)  { f = f2g; kloc = 2 * (kp - K1 / 2); }
        else                          { f = f3;  kloc = 2 * (kp - (K1 + K2) / 2); }
        f_s[idx] = make_float2(f[kloc * RANK + r], f[(kloc + 1) * RANK + r]);
    }
    __syncthreads();

    const ulonglong2* fsp = reinterpret_cast<const ulonglong2*>(f_s);

    const int lane = tid & 31;
    const int kL   = lane & 15;
    const int h    = lane >> 4;            // half-warp: owns rows 2h, 2h+1
    const int wid  = tid >> 5;
    const int gw   = blockIdx.x * (T1 / 32) + wid;

    const uint32_t stage_base =
        (uint32_t)__cvta_generic_to_shared((char*)f_s + FS_BYTES + wid * RING_BYTES);
    const uint32_t dstoff = (uint32_t)(h * 512 + kL * 16);

    // factor bases (ulonglong2 units) for this lane's k position
    const ulonglong2* FA = fsp + kL;                          // seg1
    const ulonglong2* FB = FA + (K1 / 2) / 2;                 // seg2 (+256)
    const ulonglong2* FC = FA + ((K1 + K2) / 2) / 2;          // seg3 (+384)

    u64 acc[2][RANK];
#pragma unroll
    for (int i = 0; i < 2; i++)
#pragma unroll
        for (int j = 0; j < RANK; j++) acc[i][j] = 0ull;

    float p[2][RANK], zt[2][RANK];

    // prologue: first group's x1 chunks 0..2 into slots 0..2
    const char* rA  = (const char*)x1 + ((size_t)(gw * 4 + 2 * h) * K1) * 4 + kL * 16;
    const char* rA2 = rA + (size_t)K1 * 4;
    ISSUE(rA, rA2, 0, 0);
    ISSUE(rA, rA2, 1, 1);
    ISSUE(rA, rA2, 2, 2);

    for (int g = gw; g < NGROUPS; g += NWARPS) {
        const int row0 = g * 4;
        const int gn   = (g + NWARPS < NGROUPS) ? g + NWARPS : g;

        const char* rB  = (const char*)x2 + ((size_t)(row0 + 2 * h) * K2) * 4 + kL * 16;
        const char* rB2 = rB + (size_t)K2 * 4;
        const char* rC  = (const char*)x3 + ((size_t)(row0 + 2 * h) * K3) * 4 + kL * 16;
        const char* rC2 = rC + (size_t)K3 * 4;
        const char* rN  = (const char*)x1 + ((size_t)(gn * 4 + 2 * h) * K1) * 4 + kL * 16;
        const char* rN2 = rN + (size_t)K1 * 4;

        // ---- segment 1 (x1): global chunks t = 0..15 ----
#pragma unroll
        for (int c = 0; c < NC1; c++) {
            WAITG2();
            CONSUME(c & 3, FA + c * 16);
            if (c < NC1 - 3) ISSUE(rA, rA2, c + 3,       (c + 3) & 3);
            else             ISSUE(rB, rB2, c - (NC1-3), (c + 3) & 3);
        }
        FOLD(); REDUCE();                      // pipeline stays full underneath
#pragma unroll
        for (int i = 0; i < 2; i++)
#pragma unroll
            for (int j = 0; j < RANK; j++) p[i][j] = zt[i][j];

        // ---- segment 2 (x2): t = 16..23 ----
#pragma unroll
        for (int c = 0; c < NC2; c++) {
            WAITG2();
            CONSUME((NC1 + c) & 3, FB + c * 16);
            if (c < NC2 - 3) ISSUE(rB, rB2, c + 3,       (NC1 + c + 3) & 3);
            else             ISSUE(rC, rC2, c - (NC2-3), (NC1 + c + 3) & 3);
        }
        FOLD(); REDUCE();
#pragma unroll
        for (int i = 0; i < 2; i++)
#pragma unroll
            for (int j = 0; j < RANK; j++) p[i][j] *= zt[i][j];

        // ---- segment 3 (x3): t = 24..35, leads into next group's x1 ----
#pragma unroll
        for (int c = 0; c < NC3; c++) {
            WAITG2();
            CONSUME((NC1 + NC2 + c) & 3, FC + c * 16);
            if (c < NC3 - 3) ISSUE(rC, rC2, c + 3,       (NC1 + NC2 + c + 3) & 3);
            else             ISSUE(rN, rN2, c - (NC3-3), (NC1 + NC2 + c + 3) & 3);
        }
        FOLD(); REDUCE();
#pragma unroll
        for (int i = 0; i < 2; i++)
#pragma unroll
            for (int j = 0; j < RANK; j++) p[i][j] *= zt[i][j];

        rA = rN; rA2 = rN2;

        // write: lane kL==j of half h writes rank j of rows 2h, 2h+1
#pragma unroll
        for (int j = 0; j < RANK; j++) {
            if (kL == j) {
                y_buf[(size_t)(row0 + 2 * h)     * RANK + j] = p[0][j];
                y_buf[(size_t)(row0 + 2 * h + 1) * RANK + j] = p[1][j];
            }
        }
    }

    asm volatile("cp.async.wait_group 0;" ::: "memory");   // drain
}

// out[b, c] = sum_j y[b, j] * fout[c, j]
// 256 threads; thread t owns adjacent cols (2t, 2t+1) -> one STG.64 per row;
// 64-row tile; y transposed in smem so a row-pair is one LDS.64 broadcast;
// fout lives in registers (packed duplicate per column).
extern "C" __global__ void __launch_bounds__(T2)
arf_k2(const float* __restrict__ fout, float* __restrict__ out)
{
    __shared__ __align__(16) float yt[RANK][RTILE];   // transposed y tile

    const int t    = threadIdx.x;
    const int c0   = 2 * t;
    const int base = blockIdx.x * RTILE;

    u64 foA[RANK], foB[RANK];
#pragma unroll
    for (int j = 0; j < RANK; j++) {
        float a = fout[(size_t)c0 * RANK + j];
        float b = fout[(size_t)(c0 + 1) * RANK + j];
        foA[j] = pk2(a, a);
        foB[j] = pk2(b, b);
    }

    for (int idx = t; idx < RTILE * RANK; idx += T2) {
        int r = idx / RANK, j = idx % RANK;       // coalesced y_buf read
        yt[j][r] = y_buf[(size_t)base * RANK + idx];
    }
    __syncthreads();

#pragma unroll 4
    for (int rp = 0; rp < RTILE / 2; rp++) {
        u64 yv[RANK];
#pragma unroll
        for (int j = 0; j < RANK; j++)
            yv[j] = *reinterpret_cast<const u64*>(&yt[j][2 * rp]);  // broadcast

        u64 a = 0ull, b = 0ull;
#pragma unroll
        for (int j = 0; j < RANK; j++) {
            a = fma2(yv[j], foA[j], a);
            b = fma2(yv[j], foB[j], b);
        }
        float la, ha, lb, hb;
        upk2(a, la, ha);
        upk2(b, lb, hb);
        float2* o0 = reinterpret_cast<float2*>(out + (size_t)(base + 2 * rp) * OUTDIM);
        float2* o1 = reinterpret_cast<float2*>(out + (size_t)(base + 2 * rp + 1) * OUTDIM);
        o0[t] = make_float2(la, lb);   // STG.64, coalesced
        o1[t] = make_float2(ha, hb);
    }
}

extern "C" void kernel_launch(void* const* d_in, const int* in_sizes, int n_in,
                              void* d_out, int out_size)
{
    const float* x1   = (const float*)d_in[0];
    const float* x2   = (const float*)d_in[1];
    const float* x3   = (const float*)d_in[2];
    const float* f1   = (const float*)d_in[3];
    const float* f2   = (const float*)d_in[4];
    const float* f3   = (const float*)d_in[5];
    const float* fout = (const float*)d_in[6];
    float* out = (float*)d_out;

    cudaFuncSetAttribute(arf_k1,
                         cudaFuncAttributeMaxDynamicSharedMemorySize, SMEM1);

    arf_k1<<<GRID1, T1, SMEM1>>>(x1, x2, x3, f1, f2, f3);
    arf_k2<<<GRID2, T2>>>(fout, out);
}